// round 8
// baseline (speedup 1.0000x reference)
#include <cuda_runtime.h>
#include <math.h>

#define Bv    8
#define Sv    4096
#define Tv    512
#define HIDv  512
#define HEADSv 8
#define DKv   64

typedef unsigned long long u64;

// Scratch (allocation-free: __device__ globals)
__device__ float g_Q[Bv * Tv * HIDv];        // 8 MB
__device__ float g_K[Bv * Sv * HIDv];        // 64 MB
__device__ float g_V[Bv * Sv * HIDv];        // 64 MB
__device__ float g_ctx[Bv * Tv * HIDv];      // 8 MB

// ---------------- packed f32x2 helpers (FFMA2 path) ----------------
__device__ __forceinline__ u64 pack2(float x, float y) {
    u64 d; asm("mov.b64 %0, {%1, %2};" : "=l"(d) : "f"(x), "f"(y)); return d;
}
__device__ __forceinline__ u64 pdup(float x) { return pack2(x, x); }
__device__ __forceinline__ void unpack2(u64 v, float& x, float& y) {
    asm("mov.b64 {%0, %1}, %2;" : "=f"(x), "=f"(y) : "l"(v));
}
__device__ __forceinline__ u64 fma2(u64 a, u64 b, u64 c) {
    u64 d; asm("fma.rn.f32x2 %0, %1, %2, %3;" : "=l"(d) : "l"(a), "l"(b), "l"(c)); return d;
}
__device__ __forceinline__ u64 mul2(u64 a, u64 b) {
    u64 d; asm("mul.rn.f32x2 %0, %1, %2;" : "=l"(d) : "l"(a), "l"(b)); return d;
}
__device__ __forceinline__ void sts64(float* p, u64 v) {
    asm volatile("st.shared.b64 [%0], %1;" :: "l"(__cvta_generic_to_shared(p)), "l"(v) : "memory");
}

// FMA-pipe exp (avoids MUFU throughput wall). Valid for x <= 0; exact at 0.
__device__ __forceinline__ float fast_exp(float x) {
    float y = fmaxf(x * 1.4426950408889634f, -126.0f);
    float n = rintf(y);
    float r = y - n;
    float q = 1.5403530394e-4f;
    q = fmaf(q, r, 1.3333558146e-3f);
    q = fmaf(q, r, 9.6181291076e-3f);
    q = fmaf(q, r, 5.5504108664e-2f);
    q = fmaf(q, r, 2.4022650696e-1f);
    q = fmaf(q, r, 6.9314718056e-1f);
    q = fmaf(q, r, 1.0f);
    return q * __int_as_float(((int)n + 127) << 23);
}

// ---------------------------------------------------------------------------
// C[M,512] = A[M,512] @ W[512,512]^T + bias   (row-major, K contiguous)
// 128x128 tile, BK=16, 256 threads, 8x8 microtile.
// Accumulators packed over m-PAIRS; A supplies natural LDS.128 pairs, W is
// stored DUPLICATED in smem so LDS.128 yields ready dup'd f32x2 operands.
// Inner loop: 6 LDS.128 + 32 FFMA2 per 64 MACs, zero packing MOVs.
// ---------------------------------------------------------------------------
__global__ __launch_bounds__(256, 2) void gemm_bias_kernel(
    const float* __restrict__ A, const float* __restrict__ W,
    const float* __restrict__ bias, float* __restrict__ C, int M)
{
    const int BK = 16, AP = 132, WP = 264;
    __shared__ float As[BK * AP];     // As[k][m], natural
    __shared__ float Wsd[BK * WP];    // Wsd[k][2n] = Wsd[k][2n+1] = W[n0+n][k]

    const int tid = threadIdx.x;
    const int tx = tid & 15, ty = tid >> 4;
    const int m0 = blockIdx.y * 128;
    const int n0 = blockIdx.x * 128;

    u64 acc2[4][8];
    #pragma unroll
    for (int i = 0; i < 4; i++)
        #pragma unroll
        for (int j = 0; j < 8; j++) acc2[i][j] = 0ull;

    for (int k0 = 0; k0 < 512; k0 += BK) {
        #pragma unroll
        for (int r = 0; r < 2; r++) {
            int f   = tid + r * 256;
            int row = f >> 2;               // 0..127
            int kq  = (f & 3) * 4;          // 0,4,8,12
            float4 a = *(const float4*)&A[(size_t)(m0 + row) * 512 + k0 + kq];
            As[(kq + 0) * AP + row] = a.x;
            As[(kq + 1) * AP + row] = a.y;
            As[(kq + 2) * AP + row] = a.z;
            As[(kq + 3) * AP + row] = a.w;
            float4 w = *(const float4*)&W[(size_t)(n0 + row) * 512 + k0 + kq];
            sts64(&Wsd[(kq + 0) * WP + 2 * row], pdup(w.x));
            sts64(&Wsd[(kq + 1) * WP + 2 * row], pdup(w.y));
            sts64(&Wsd[(kq + 2) * WP + 2 * row], pdup(w.z));
            sts64(&Wsd[(kq + 3) * WP + 2 * row], pdup(w.w));
        }
        __syncthreads();

        #pragma unroll
        for (int kk = 0; kk < BK; kk++) {
            ulonglong2 a0 = *(const ulonglong2*)&As[kk * AP + ty * 8];
            ulonglong2 a1 = *(const ulonglong2*)&As[kk * AP + ty * 8 + 4];
            u64 ap[4] = {a0.x, a0.y, a1.x, a1.y};      // m-pairs
            ulonglong2 w0 = *(const ulonglong2*)&Wsd[kk * WP + 2 * (tx * 8)];
            ulonglong2 w1 = *(const ulonglong2*)&Wsd[kk * WP + 2 * (tx * 8) + 4];
            ulonglong2 w2 = *(const ulonglong2*)&Wsd[kk * WP + 2 * (tx * 8) + 8];
            ulonglong2 w3 = *(const ulonglong2*)&Wsd[kk * WP + 2 * (tx * 8) + 12];
            u64 wd[8] = {w0.x, w0.y, w1.x, w1.y, w2.x, w2.y, w3.x, w3.y};  // dup'd n
            #pragma unroll
            for (int i = 0; i < 4; i++)
                #pragma unroll
                for (int j = 0; j < 8; j++)
                    acc2[i][j] = fma2(ap[i], wd[j], acc2[i][j]);
        }
        __syncthreads();
    }

    float bb[8];
    *(float4*)&bb[0] = *(const float4*)&bias[n0 + tx * 8];
    *(float4*)&bb[4] = *(const float4*)&bias[n0 + tx * 8 + 4];
    #pragma unroll
    for (int i = 0; i < 4; i++) {
        float lo[8], hi[8];
        #pragma unroll
        for (int j = 0; j < 8; j++) unpack2(acc2[i][j], lo[j], hi[j]);
        float4 e0, e1, o0, o1;
        e0.x = lo[0] + bb[0]; e0.y = lo[1] + bb[1]; e0.z = lo[2] + bb[2]; e0.w = lo[3] + bb[3];
        e1.x = lo[4] + bb[4]; e1.y = lo[5] + bb[5]; e1.z = lo[6] + bb[6]; e1.w = lo[7] + bb[7];
        o0.x = hi[0] + bb[0]; o0.y = hi[1] + bb[1]; o0.z = hi[2] + bb[2]; o0.w = hi[3] + bb[3];
        o1.x = hi[4] + bb[4]; o1.y = hi[5] + bb[5]; o1.z = hi[6] + bb[6]; o1.w = hi[7] + bb[7];
        size_t be = (size_t)(m0 + ty * 8 + 2 * i) * 512 + n0 + tx * 8;
        size_t bo = be + 512;
        *(float4*)&C[be]     = e0;  *(float4*)&C[be + 4] = e1;
        *(float4*)&C[bo]     = o0;  *(float4*)&C[bo + 4] = o1;
    }
}

// ---------------------------------------------------------------------------
// Flash attention: one block per (256-query tile, head, batch) = 128 blocks.
// tx in [0,8): 8 key/d cols each; ty in [0,32): 8 queries each.
// Accumulators packed over query-PAIRS. K and V stored duplicated in smem;
// Q and P supply natural pairs. Inner loops: 6 LDS.128 + 32 FFMA2 / 64 MACs.
// ---------------------------------------------------------------------------
__global__ __launch_bounds__(256) void attn_kernel(const int* __restrict__ mask)
{
    extern __shared__ float sm[];
    float* Qs    = sm;                    // [64][260]  Q k-major, natural
    float* Kd    = Qs + 64 * 260;         // [64][136]  K k-major, duplicated
    float* Vsd   = Kd + 64 * 136;         // [64][136]  V s-major, duplicated
    float* Ps    = Vsd + 64 * 136;        // [64][260]  P s-major, natural
    float* mnegd = Ps + 64 * 260;         // [128]      mask add, duplicated

    const int tid = threadIdx.x;
    const int tx = tid & 7;               // key/d group
    const int ty = tid >> 3;              // query group (0..31)
    const int t0 = blockIdx.x * 256;
    const int h  = blockIdx.y;
    const int b  = blockIdx.z;

    // Load Q tile 256x64, transposed to k-major (natural, not dup'd).
    #pragma unroll
    for (int r = 0; r < 16; r++) {
        int idx = tid + r * 256;
        int row = idx >> 4;               // 0..255
        int c4  = (idx & 15) * 4;
        float4 q = *(const float4*)&g_Q[((size_t)(b * Tv + t0 + row)) * HIDv + h * DKv + c4];
        Qs[(c4 + 0) * 260 + row] = q.x;
        Qs[(c4 + 1) * 260 + row] = q.y;
        Qs[(c4 + 2) * 260 + row] = q.z;
        Qs[(c4 + 3) * 260 + row] = q.w;
    }

    float rowM[8], rowL[8];
    #pragma unroll
    for (int i = 0; i < 8; i++) { rowM[i] = -1e30f; rowL[i] = 0.0f; }

    u64 acc2[4][8];
    #pragma unroll
    for (int i = 0; i < 4; i++)
        #pragma unroll
        for (int j = 0; j < 8; j++) acc2[i][j] = 0ull;

    const u64 c18d = pdup(0.125f);
    __syncthreads();

    for (int s0 = 0; s0 < Sv; s0 += 64) {
        // Load K (k-major, dup'd), V (s-major, dup'd), mask strip (dup'd).
        #pragma unroll
        for (int r = 0; r < 4; r++) {
            int idx = tid + r * 256;
            int row = idx >> 4;           // 0..63
            int c4  = (idx & 15) * 4;
            size_t g = ((size_t)(b * Sv + s0 + row)) * HIDv + h * DKv + c4;
            float4 k = *(const float4*)&g_K[g];
            sts64(&Kd[(c4 + 0) * 136 + 2 * row], pdup(k.x));
            sts64(&Kd[(c4 + 1) * 136 + 2 * row], pdup(k.y));
            sts64(&Kd[(c4 + 2) * 136 + 2 * row], pdup(k.z));
            sts64(&Kd[(c4 + 3) * 136 + 2 * row], pdup(k.w));
            float4 v = *(const float4*)&g_V[g];
            sts64(&Vsd[row * 136 + 2 * c4 + 0], pdup(v.x));
            sts64(&Vsd[row * 136 + 2 * c4 + 2], pdup(v.y));
            sts64(&Vsd[row * 136 + 2 * c4 + 4], pdup(v.z));
            sts64(&Vsd[row * 136 + 2 * c4 + 6], pdup(v.w));
        }
        if (tid < 64) {
            float mv = (mask[b * Sv + s0 + tid] != 0) ? 0.0f : -1e20f;
            sts64(&mnegd[2 * tid], pdup(mv));
        }
        __syncthreads();

        // QK^T: sc2[qpair][key], q-pairs natural from Qs, keys dup'd from Kd.
        u64 sc2[4][8];
        #pragma unroll
        for (int i = 0; i < 4; i++)
            #pragma unroll
            for (int j = 0; j < 8; j++) sc2[i][j] = 0ull;

        #pragma unroll 8
        for (int kk = 0; kk < 64; kk++) {
            ulonglong2 q0 = *(const ulonglong2*)&Qs[kk * 260 + ty * 8];
            ulonglong2 q1 = *(const ulonglong2*)&Qs[kk * 260 + ty * 8 + 4];
            u64 qp[4] = {q0.x, q0.y, q1.x, q1.y};
            ulonglong2 k0 = *(const ulonglong2*)&Kd[kk * 136 + 2 * (tx * 8)];
            ulonglong2 k1 = *(const ulonglong2*)&Kd[kk * 136 + 2 * (tx * 8) + 4];
            ulonglong2 k2 = *(const ulonglong2*)&Kd[kk * 136 + 2 * (tx * 8) + 8];
            ulonglong2 k3 = *(const ulonglong2*)&Kd[kk * 136 + 2 * (tx * 8) + 12];
            u64 kd[8] = {k0.x, k0.y, k1.x, k1.y, k2.x, k2.y, k3.x, k3.y};
            #pragma unroll
            for (int i = 0; i < 4; i++)
                #pragma unroll
                for (int j = 0; j < 8; j++)
                    sc2[i][j] = fma2(qp[i], kd[j], sc2[i][j]);
        }

        // scale + mask (mask dup'd per key)
        {
            ulonglong2 m0 = *(const ulonglong2*)&mnegd[2 * (tx * 8)];
            ulonglong2 m1 = *(const ulonglong2*)&mnegd[2 * (tx * 8) + 4];
            ulonglong2 m2 = *(const ulonglong2*)&mnegd[2 * (tx * 8) + 8];
            ulonglong2 m3 = *(const ulonglong2*)&mnegd[2 * (tx * 8) + 12];
            u64 mm[8] = {m0.x, m0.y, m1.x, m1.y, m2.x, m2.y, m3.x, m3.y};
            #pragma unroll
            for (int i = 0; i < 4; i++)
                #pragma unroll
                for (int j = 0; j < 8; j++)
                    sc2[i][j] = fma2(sc2[i][j], c18d, mm[j]);
        }

        // Online softmax: per query-pair, both rows; packed rescale of acc.
        #pragma unroll
        for (int i = 0; i < 4; i++) {
            float se_[8], so_[8];
            #pragma unroll
            for (int j = 0; j < 8; j++) unpack2(sc2[i][j], se_[j], so_[j]);

            // even query (lo lane of pack)
            float mxe = fmaxf(fmaxf(fmaxf(se_[0], se_[1]), fmaxf(se_[2], se_[3])),
                              fmaxf(fmaxf(se_[4], se_[5]), fmaxf(se_[6], se_[7])));
            float mxo = fmaxf(fmaxf(fmaxf(so_[0], so_[1]), fmaxf(so_[2], so_[3])),
                              fmaxf(fmaxf(so_[4], so_[5]), fmaxf(so_[6], so_[7])));
            #pragma unroll
            for (int o = 4; o >= 1; o >>= 1) {
                mxe = fmaxf(mxe, __shfl_xor_sync(0xffffffffu, mxe, o, 8));
                mxo = fmaxf(mxo, __shfl_xor_sync(0xffffffffu, mxo, o, 8));
            }
            int qe = 2 * i, qo = 2 * i + 1;
            float mne = fmaxf(rowM[qe], mxe);
            float mno = fmaxf(rowM[qo], mxo);
            float fe = fast_exp(rowM[qe] - mne);
            float fo = fast_exp(rowM[qo] - mno);
            rowM[qe] = mne; rowM[qo] = mno;

            float pe[8], po[8], sse = 0.0f, sso = 0.0f;
            #pragma unroll
            for (int j = 0; j < 8; j++) {
                pe[j] = fast_exp(se_[j] - mne); sse += pe[j];
                po[j] = fast_exp(so_[j] - mno); sso += po[j];
            }
            #pragma unroll
            for (int o = 4; o >= 1; o >>= 1) {
                sse += __shfl_xor_sync(0xffffffffu, sse, o, 8);
                sso += __shfl_xor_sync(0xffffffffu, sso, o, 8);
            }
            rowL[qe] = rowL[qe] * fe + sse;
            rowL[qo] = rowL[qo] * fo + sso;

            u64 f2 = pack2(fe, fo);
            #pragma unroll
            for (int j = 0; j < 8; j++) acc2[i][j] = mul2(acc2[i][j], f2);

            // store P pairs: Ps[key][query], query pair contiguous
            #pragma unroll
            for (int j = 0; j < 8; j++)
                sts64(&Ps[(tx * 8 + j) * 260 + ty * 8 + 2 * i], pack2(pe[j], po[j]));
        }
        __syncthreads();

        // acc += P @ V : p-pairs natural from Ps, V dup'd from Vsd.
        #pragma unroll 4
        for (int s = 0; s < 64; s++) {
            ulonglong2 p0 = *(const ulonglong2*)&Ps[s * 260 + ty * 8];
            ulonglong2 p1 = *(const ulonglong2*)&Ps[s * 260 + ty * 8 + 4];
            u64 pp[4] = {p0.x, p0.y, p1.x, p1.y};
            ulonglong2 v0 = *(const ulonglong2*)&Vsd[s * 136 + 2 * (tx * 8)];
            ulonglong2 v1 = *(const ulonglong2*)&Vsd[s * 136 + 2 * (tx * 8) + 4];
            ulonglong2 v2 = *(const ulonglong2*)&Vsd[s * 136 + 2 * (tx * 8) + 8];
            ulonglong2 v3 = *(const ulonglong2*)&Vsd[s * 136 + 2 * (tx * 8) + 12];
            u64 vd[8] = {v0.x, v0.y, v1.x, v1.y, v2.x, v2.y, v3.x, v3.y};
            #pragma unroll
            for (int i = 0; i < 4; i++)
                #pragma unroll
                for (int j = 0; j < 8; j++)
                    acc2[i][j] = fma2(pp[i], vd[j], acc2[i][j]);
        }
        __syncthreads();
    }

    // normalize + write ctx (two query rows per pair)
    #pragma unroll
    for (int i = 0; i < 4; i++) {
        float inve = 1.0f / rowL[2 * i];
        float invo = 1.0f / rowL[2 * i + 1];
        float lo[8], hi[8];
        #pragma unroll
        for (int j = 0; j < 8; j++) unpack2(acc2[i][j], lo[j], hi[j]);
        float4 e0, e1, o0, o1;
        e0.x = lo[0] * inve; e0.y = lo[1] * inve; e0.z = lo[2] * inve; e0.w = lo[3] * inve;
        e1.x = lo[4] * inve; e1.y = lo[5] * inve; e1.z = lo[6] * inve; e1.w = lo[7] * inve;
        o0.x = hi[0] * invo; o0.y = hi[1] * invo; o0.z = hi[2] * invo; o0.w = hi[3] * invo;
        o1.x = hi[4] * invo; o1.y = hi[5] * invo; o1.z = hi[6] * invo; o1.w = hi[7] * invo;
        size_t be = ((size_t)(b * Tv + t0 + ty * 8 + 2 * i)) * HIDv + h * DKv + tx * 8;
        size_t bo = be + HIDv;
        *(float4*)&g_ctx[be]     = e0;  *(float4*)&g_ctx[be + 4] = e1;
        *(float4*)&g_ctx[bo]     = o0;  *(float4*)&g_ctx[bo + 4] = o1;
    }
}

// ---------------------------------------------------------------------------

extern "C" void kernel_launch(void* const* d_in, const int* in_sizes, int n_in,
                              void* d_out, int out_size)
{
    const float* inputs  = (const float*)d_in[0];
    const float* targets = (const float*)d_in[1];
    const int*   mask    = (const int*)d_in[2];     // bool widened to int32
    const float* Wq = (const float*)d_in[3];
    const float* bq = (const float*)d_in[4];
    const float* Wk = (const float*)d_in[5];
    const float* bk = (const float*)d_in[6];
    const float* Wv = (const float*)d_in[7];
    const float* bv = (const float*)d_in[8];
    const float* Wo = (const float*)d_in[9];
    const float* bo = (const float*)d_in[10];
    float* out = (float*)d_out;

    float *pQ, *pK, *pV, *pC;
    cudaGetSymbolAddress((void**)&pQ, g_Q);
    cudaGetSymbolAddress((void**)&pK, g_K);
    cudaGetSymbolAddress((void**)&pV, g_V);
    cudaGetSymbolAddress((void**)&pC, g_ctx);

    const int ATTN_SMEM = (64 * 260 + 64 * 136 + 64 * 136 + 64 * 260 + 128) * (int)sizeof(float);
    cudaFuncSetAttribute(attn_kernel, cudaFuncAttributeMaxDynamicSharedMemorySize, ATTN_SMEM);

    dim3 blk256(256);

    // Q = targets @ Wq^T + bq    (M = B*T = 4096)
    gemm_bias_kernel<<<dim3(4, 32), blk256>>>(targets, Wq, bq, pQ, Bv * Tv);
    // K = inputs @ Wk^T + bk     (M = B*S = 32768)
    gemm_bias_kernel<<<dim3(4, 256), blk256>>>(inputs, Wk, bk, pK, Bv * Sv);
    // V = inputs @ Wv^T + bv
    gemm_bias_kernel<<<dim3(4, 256), blk256>>>(inputs, Wv, bv, pV, Bv * Sv);
    // attention -> g_ctx   (256-query tiles: 2 per (b,h) -> 128 blocks)
    attn_kernel<<<dim3(Tv / 256, HEADSv, Bv), blk256, ATTN_SMEM>>>(mask);
    // out = ctx @ Wo^T + bo
    gemm_bias_kernel<<<dim3(4, 32), blk256>>>(pC, Wo, bo, out, Bv * Tv);
}

// round 9
// speedup vs baseline: 2.7256x; 2.7256x over previous
#include <cuda_runtime.h>
#include <math.h>

#define Bv    8
#define Sv    4096
#define Tv    512
#define HIDv  512
#define HEADSv 8
#define DKv   64

typedef unsigned long long u64;

// Scratch (allocation-free: __device__ globals)
__device__ float g_Q[Bv * Tv * HIDv];        // 8 MB
__device__ float g_K[Bv * Sv * HIDv];        // 64 MB
__device__ float g_V[Bv * Sv * HIDv];        // 64 MB
__device__ float g_ctx[Bv * Tv * HIDv];      // 8 MB

// ---------------- packed f32x2 helpers (FFMA2 path) ----------------
__device__ __forceinline__ u64 pack2(float x, float y) {
    u64 d; asm("mov.b64 %0, {%1, %2};" : "=l"(d) : "f"(x), "f"(y)); return d;
}
__device__ __forceinline__ u64 pdup(float x) { return pack2(x, x); }
__device__ __forceinline__ void unpack2(u64 v, float& x, float& y) {
    asm("mov.b64 {%0, %1}, %2;" : "=f"(x), "=f"(y) : "l"(v));
}
__device__ __forceinline__ u64 fma2(u64 a, u64 b, u64 c) {
    u64 d; asm("fma.rn.f32x2 %0, %1, %2, %3;" : "=l"(d) : "l"(a), "l"(b), "l"(c)); return d;
}
__device__ __forceinline__ u64 mul2(u64 a, u64 b) {
    u64 d; asm("mul.rn.f32x2 %0, %1, %2;" : "=l"(d) : "l"(a), "l"(b)); return d;
}

// FMA-pipe exp (avoids MUFU throughput wall). Valid for x <= 0; exact at 0.
__device__ __forceinline__ float fast_exp(float x) {
    float y = fmaxf(x * 1.4426950408889634f, -126.0f);
    float n = rintf(y);
    float r = y - n;
    float q = 1.5403530394e-4f;
    q = fmaf(q, r, 1.3333558146e-3f);
    q = fmaf(q, r, 9.6181291076e-3f);
    q = fmaf(q, r, 5.5504108664e-2f);
    q = fmaf(q, r, 2.4022650696e-1f);
    q = fmaf(q, r, 6.9314718056e-1f);
    q = fmaf(q, r, 1.0f);
    return q * __int_as_float(((int)n + 127) << 23);
}

// ---------------------------------------------------------------------------
// C[M,512] = A[M,512] @ W[512,512]^T + bias   (row-major, K contiguous)
// 128x128 tile, BK=16, 256 threads, 8x8 microtile, packed f32x2 FMAs.
// 2 CTAs/SM (smem 16.9KB, regs capped at 128) so barrier/LDS bubbles overlap.
// ---------------------------------------------------------------------------
__global__ __launch_bounds__(256, 2) void gemm_bias_kernel(
    const float* __restrict__ A, const float* __restrict__ W,
    const float* __restrict__ bias, float* __restrict__ C, int M)
{
    const int BK = 16, LDSP = 132;                // 128+4, keeps 16B alignment
    __shared__ float As[BK * LDSP];
    __shared__ float Ws[BK * LDSP];

    const int tid = threadIdx.x;
    const int tx = tid & 15, ty = tid >> 4;
    const int m0 = blockIdx.y * 128;
    const int n0 = blockIdx.x * 128;

    u64 acc2[8][4];
    #pragma unroll
    for (int i = 0; i < 8; i++)
        #pragma unroll
        for (int j = 0; j < 4; j++) acc2[i][j] = 0ull;

    for (int k0 = 0; k0 < 512; k0 += BK) {
        #pragma unroll
        for (int r = 0; r < 2; r++) {
            int f   = tid + r * 256;
            int row = f >> 2;
            int kq  = (f & 3) * 4;
            float4 a = *(const float4*)&A[(size_t)(m0 + row) * 512 + k0 + kq];
            As[(kq + 0) * LDSP + row] = a.x;
            As[(kq + 1) * LDSP + row] = a.y;
            As[(kq + 2) * LDSP + row] = a.z;
            As[(kq + 3) * LDSP + row] = a.w;
            float4 w = *(const float4*)&W[(size_t)(n0 + row) * 512 + k0 + kq];
            Ws[(kq + 0) * LDSP + row] = w.x;
            Ws[(kq + 1) * LDSP + row] = w.y;
            Ws[(kq + 2) * LDSP + row] = w.z;
            Ws[(kq + 3) * LDSP + row] = w.w;
        }
        __syncthreads();

        #pragma unroll
        for (int kk = 0; kk < BK; kk++) {
            float4 a0 = *(const float4*)&As[kk * LDSP + ty * 8];
            float4 a1 = *(const float4*)&As[kk * LDSP + ty * 8 + 4];
            ulonglong2 w0 = *(const ulonglong2*)&Ws[kk * LDSP + tx * 8];
            ulonglong2 w1 = *(const ulonglong2*)&Ws[kk * LDSP + tx * 8 + 4];
            u64 ww[4] = {w0.x, w0.y, w1.x, w1.y};
            u64 a2[8];
            a2[0] = pdup(a0.x); a2[1] = pdup(a0.y);
            a2[2] = pdup(a0.z); a2[3] = pdup(a0.w);
            a2[4] = pdup(a1.x); a2[5] = pdup(a1.y);
            a2[6] = pdup(a1.z); a2[7] = pdup(a1.w);
            #pragma unroll
            for (int i = 0; i < 8; i++)
                #pragma unroll
                for (int j = 0; j < 4; j++)
                    acc2[i][j] = fma2(a2[i], ww[j], acc2[i][j]);
        }
        __syncthreads();
    }

    float bb[8];
    *(float4*)&bb[0] = *(const float4*)&bias[n0 + tx * 8];
    *(float4*)&bb[4] = *(const float4*)&bias[n0 + tx * 8 + 4];
    #pragma unroll
    for (int i = 0; i < 8; i++) {
        float o[8];
        unpack2(acc2[i][0], o[0], o[1]);
        unpack2(acc2[i][1], o[2], o[3]);
        unpack2(acc2[i][2], o[4], o[5]);
        unpack2(acc2[i][3], o[6], o[7]);
        float4 s0, s1;
        s0.x = o[0] + bb[0]; s0.y = o[1] + bb[1];
        s0.z = o[2] + bb[2]; s0.w = o[3] + bb[3];
        s1.x = o[4] + bb[4]; s1.y = o[5] + bb[5];
        s1.z = o[6] + bb[6]; s1.w = o[7] + bb[7];
        size_t base = (size_t)(m0 + ty * 8 + i) * 512 + n0 + tx * 8;
        *(float4*)&C[base]     = s0;
        *(float4*)&C[base + 4] = s1;
    }
}

// ---------------------------------------------------------------------------
// Flash attention: one block per (256-query tile, head, batch) = 128 blocks.
// 8x8 microtile (tx: 8 key/d groups, ty: 32 query groups), packed f32x2 FMAs,
// FMA-pipe exp, P stored transposed with XOR swizzle for conflict-free loads.
// (UNCHANGED from the 1873us round-7 kernel.)
// ---------------------------------------------------------------------------
__global__ __launch_bounds__(256) void attn_kernel(const int* __restrict__ mask)
{
    extern __shared__ float sm[];
    float* Qs   = sm;                    // [64][260]  Q k-major
    float* Ks   = Qs + 64 * 260;         // [64][68]   K k-major
    float* Vs   = Ks + 64 * 68;          // [64][68]   V s-major
    float* Ps   = Vs + 64 * 68;          // [64][260]  P s-major (swizzled cols)
    float* mneg = Ps + 64 * 260;         // [64]

    const int tid = threadIdx.x;
    const int tx = tid & 7;              // key/d group
    const int ty = tid >> 3;             // query group (0..31)
    const int t0 = blockIdx.x * 256;
    const int h  = blockIdx.y;
    const int b  = blockIdx.z;

    // Load Q tile 256x64, transposed to k-major.
    #pragma unroll
    for (int r = 0; r < 16; r++) {
        int idx = tid + r * 256;
        int row = idx >> 4;              // 0..255
        int c4  = (idx & 15) * 4;
        float4 q = *(const float4*)&g_Q[((size_t)(b * Tv + t0 + row)) * HIDv + h * DKv + c4];
        Qs[(c4 + 0) * 260 + row] = q.x;
        Qs[(c4 + 1) * 260 + row] = q.y;
        Qs[(c4 + 2) * 260 + row] = q.z;
        Qs[(c4 + 3) * 260 + row] = q.w;
    }

    float rowM[8], rowL[8];
    #pragma unroll
    for (int i = 0; i < 8; i++) { rowM[i] = -1e30f; rowL[i] = 0.0f; }

    u64 acc2[8][4];
    #pragma unroll
    for (int i = 0; i < 8; i++)
        #pragma unroll
        for (int j = 0; j < 4; j++) acc2[i][j] = 0ull;

    const int Xst = (tx & 3) << 2;       // store-side swizzle constant
    __syncthreads();

    for (int s0 = 0; s0 < Sv; s0 += 64) {
        // Load K (transposed to k-major), V (natural), mask strip.
        #pragma unroll
        for (int r = 0; r < 4; r++) {
            int idx = tid + r * 256;
            int row = idx >> 4;          // 0..63
            int c4  = (idx & 15) * 4;
            size_t g = ((size_t)(b * Sv + s0 + row)) * HIDv + h * DKv + c4;
            float4 k = *(const float4*)&g_K[g];
            Ks[(c4 + 0) * 68 + row] = k.x;
            Ks[(c4 + 1) * 68 + row] = k.y;
            Ks[(c4 + 2) * 68 + row] = k.z;
            Ks[(c4 + 3) * 68 + row] = k.w;
            float4 v = *(const float4*)&g_V[g];
            *(float4*)&Vs[row * 68 + c4] = v;
        }
        if (tid < 64) mneg[tid] = (mask[b * Sv + s0 + tid] != 0) ? 0.0f : -1e20f;
        __syncthreads();

        // QK^T: sc2[i][j] packed over key-pairs.
        u64 sc2[8][4];
        #pragma unroll
        for (int i = 0; i < 8; i++)
            #pragma unroll
            for (int j = 0; j < 4; j++) sc2[i][j] = 0ull;

        #pragma unroll 8
        for (int kk = 0; kk < 64; kk++) {
            float4 a0 = *(const float4*)&Qs[kk * 260 + ty * 8];
            float4 a1 = *(const float4*)&Qs[kk * 260 + ty * 8 + 4];
            ulonglong2 b0 = *(const ulonglong2*)&Ks[kk * 68 + tx * 8];
            ulonglong2 b1 = *(const ulonglong2*)&Ks[kk * 68 + tx * 8 + 4];
            u64 bb2[4] = {b0.x, b0.y, b1.x, b1.y};
            u64 a2[8];
            a2[0] = pdup(a0.x); a2[1] = pdup(a0.y);
            a2[2] = pdup(a0.z); a2[3] = pdup(a0.w);
            a2[4] = pdup(a1.x); a2[5] = pdup(a1.y);
            a2[6] = pdup(a1.z); a2[7] = pdup(a1.w);
            #pragma unroll
            for (int i = 0; i < 8; i++)
                #pragma unroll
                for (int j = 0; j < 4; j++)
                    sc2[i][j] = fma2(a2[i], bb2[j], sc2[i][j]);
        }

        // scale + mask (packed)
        {
            ulonglong2 m0 = *(const ulonglong2*)&mneg[tx * 8];
            ulonglong2 m1 = *(const ulonglong2*)&mneg[tx * 8 + 4];
            u64 mm[4] = {m0.x, m0.y, m1.x, m1.y};
            u64 c18 = pdup(0.125f);
            #pragma unroll
            for (int i = 0; i < 8; i++)
                #pragma unroll
                for (int j = 0; j < 4; j++)
                    sc2[i][j] = fma2(sc2[i][j], c18, mm[j]);
        }

        // Online softmax per row (8 lanes per row; shfl width 8), store P transposed.
        #pragma unroll
        for (int i = 0; i < 8; i++) {
            float s8[8];
            unpack2(sc2[i][0], s8[0], s8[1]);
            unpack2(sc2[i][1], s8[2], s8[3]);
            unpack2(sc2[i][2], s8[4], s8[5]);
            unpack2(sc2[i][3], s8[6], s8[7]);
            float mx = fmaxf(fmaxf(fmaxf(s8[0], s8[1]), fmaxf(s8[2], s8[3])),
                             fmaxf(fmaxf(s8[4], s8[5]), fmaxf(s8[6], s8[7])));
            #pragma unroll
            for (int o = 4; o >= 1; o >>= 1)
                mx = fmaxf(mx, __shfl_xor_sync(0xffffffffu, mx, o, 8));

            float mnw = fmaxf(rowM[i], mx);
            float f   = fast_exp(rowM[i] - mnw);
            rowM[i] = mnw;

            float p[8], se = 0.0f;
            #pragma unroll
            for (int k = 0; k < 8; k++) { p[k] = fast_exp(s8[k] - mnw); se += p[k]; }
            #pragma unroll
            for (int o = 4; o >= 1; o >>= 1)
                se += __shfl_xor_sync(0xffffffffu, se, o, 8);
            rowL[i] = rowL[i] * f + se;

            u64 f2 = pdup(f);
            #pragma unroll
            for (int j = 0; j < 4; j++) acc2[i][j] = mul2(acc2[i][j], f2);

            int colp = (ty * 8 + i) ^ Xst;
            #pragma unroll
            for (int j = 0; j < 8; j++)
                Ps[(tx * 8 + j) * 260 + colp] = p[j];
        }
        __syncthreads();

        // acc += P @ V   (p loads de-swizzled, vectorized)
        #pragma unroll 2
        for (int g = 0; g < 8; g++) {
            const int X    = (g & 3) << 2;
            const int base = (ty * 8) ^ (X & 8);
            const int offA = base + (X & 4);          // logical i 0..3
            const int offB = base + ((X & 4) ^ 4);    // logical i 4..7
            #pragma unroll
            for (int js = 0; js < 8; js++) {
                int s = g * 8 + js;
                ulonglong2 pa = *(const ulonglong2*)&Ps[s * 260 + offA];
                ulonglong2 pb = *(const ulonglong2*)&Ps[s * 260 + offB];
                float p0, p1, p2v, p3, p4, p5, p6, p7;
                unpack2(pa.x, p0, p1); unpack2(pa.y, p2v, p3);
                unpack2(pb.x, p4, p5); unpack2(pb.y, p6, p7);
                u64 pp[8] = {pdup(p0), pdup(p1), pdup(p2v), pdup(p3),
                             pdup(p4), pdup(p5), pdup(p6),  pdup(p7)};
                ulonglong2 v0 = *(const ulonglong2*)&Vs[s * 68 + tx * 8];
                ulonglong2 v1 = *(const ulonglong2*)&Vs[s * 68 + tx * 8 + 4];
                u64 vv[4] = {v0.x, v0.y, v1.x, v1.y};
                #pragma unroll
                for (int i = 0; i < 8; i++)
                    #pragma unroll
                    for (int j = 0; j < 4; j++)
                        acc2[i][j] = fma2(pp[i], vv[j], acc2[i][j]);
            }
        }
        __syncthreads();
    }

    // normalize + write ctx
    #pragma unroll
    for (int i = 0; i < 8; i++) {
        float inv = 1.0f / rowL[i];
        float o[8];
        unpack2(acc2[i][0], o[0], o[1]);
        unpack2(acc2[i][1], o[2], o[3]);
        unpack2(acc2[i][2], o[4], o[5]);
        unpack2(acc2[i][3], o[6], o[7]);
        float4 s0, s1;
        s0.x = o[0] * inv; s0.y = o[1] * inv; s0.z = o[2] * inv; s0.w = o[3] * inv;
        s1.x = o[4] * inv; s1.y = o[5] * inv; s1.z = o[6] * inv; s1.w = o[7] * inv;
        size_t base = ((size_t)(b * Tv + t0 + ty * 8 + i)) * HIDv + h * DKv + tx * 8;
        *(float4*)&g_ctx[base]     = s0;
        *(float4*)&g_ctx[base + 4] = s1;
    }
}

// ---------------------------------------------------------------------------

extern "C" void kernel_launch(void* const* d_in, const int* in_sizes, int n_in,
                              void* d_out, int out_size)
{
    const float* inputs  = (const float*)d_in[0];
    const float* targets = (const float*)d_in[1];
    const int*   mask    = (const int*)d_in[2];     // bool widened to int32
    const float* Wq = (const float*)d_in[3];
    const float* bq = (const float*)d_in[4];
    const float* Wk = (const float*)d_in[5];
    const float* bk = (const float*)d_in[6];
    const float* Wv = (const float*)d_in[7];
    const float* bv = (const float*)d_in[8];
    const float* Wo = (const float*)d_in[9];
    const float* bo = (const float*)d_in[10];
    float* out = (float*)d_out;

    float *pQ, *pK, *pV, *pC;
    cudaGetSymbolAddress((void**)&pQ, g_Q);
    cudaGetSymbolAddress((void**)&pK, g_K);
    cudaGetSymbolAddress((void**)&pV, g_V);
    cudaGetSymbolAddress((void**)&pC, g_ctx);

    const int ATTN_SMEM = (64 * 260 + 64 * 68 + 64 * 68 + 64 * 260 + 64) * (int)sizeof(float);
    cudaFuncSetAttribute(attn_kernel, cudaFuncAttributeMaxDynamicSharedMemorySize, ATTN_SMEM);

    dim3 blk256(256);

    // Q = targets @ Wq^T + bq    (M = B*T = 4096)
    gemm_bias_kernel<<<dim3(4, 32), blk256>>>(targets, Wq, bq, pQ, Bv * Tv);
    // K = inputs @ Wk^T + bk     (M = B*S = 32768)
    gemm_bias_kernel<<<dim3(4, 256), blk256>>>(inputs, Wk, bk, pK, Bv * Sv);
    // V = inputs @ Wv^T + bv
    gemm_bias_kernel<<<dim3(4, 256), blk256>>>(inputs, Wv, bv, pV, Bv * Sv);
    // attention -> g_ctx   (256-query tiles: 2 per (b,h) -> 128 blocks)
    attn_kernel<<<dim3(Tv / 256, HEADSv, Bv), blk256, ATTN_SMEM>>>(mask);
    // out = ctx @ Wo^T + bo
    gemm_bias_kernel<<<dim3(4, 32), blk256>>>(pC, Wo, bo, out, Bv * Tv);
}

// round 11
// speedup vs baseline: 2.8020x; 1.0280x over previous
#include <cuda_runtime.h>
#include <cuda_bf16.h>
#include <math.h>

#define Bv    8
#define Sv    4096
#define Tv    512
#define HIDv  512
#define HEADSv 8
#define DKv   64

typedef unsigned long long u64;

// ------------------------- scratch (__device__ globals) --------------------
__device__ float g_Q[Bv * Tv * HIDv];
__device__ float g_K[Bv * Sv * HIDv];
__device__ float g_V[Bv * Sv * HIDv];
__device__ float g_ctx[Bv * Tv * HIDv];
__device__ __nv_bfloat16 g_in_hi[Bv * Sv * HIDv];
__device__ __nv_bfloat16 g_in_lo[Bv * Sv * HIDv];
__device__ __nv_bfloat16 g_tg_hi[Bv * Tv * HIDv];
__device__ __nv_bfloat16 g_tg_lo[Bv * Tv * HIDv];
__device__ __nv_bfloat16 g_cx_hi[Bv * Tv * HIDv];
__device__ __nv_bfloat16 g_cx_lo[Bv * Tv * HIDv];
__device__ __nv_bfloat16 g_w_hi[4 * HIDv * HIDv];
__device__ __nv_bfloat16 g_w_lo[4 * HIDv * HIDv];

// ---------------- packed f32x2 helpers (FFMA2, attention) ------------------
__device__ __forceinline__ u64 pack2(float x, float y) {
    u64 d; asm("mov.b64 %0, {%1, %2};" : "=l"(d) : "f"(x), "f"(y)); return d;
}
__device__ __forceinline__ u64 pdup(float x) { return pack2(x, x); }
__device__ __forceinline__ void unpack2(u64 v, float& x, float& y) {
    asm("mov.b64 {%0, %1}, %2;" : "=f"(x), "=f"(y) : "l"(v));
}
__device__ __forceinline__ u64 fma2(u64 a, u64 b, u64 c) {
    u64 d; asm("fma.rn.f32x2 %0, %1, %2, %3;" : "=l"(d) : "l"(a), "l"(b), "l"(c)); return d;
}
__device__ __forceinline__ u64 mul2(u64 a, u64 b) {
    u64 d; asm("mul.rn.f32x2 %0, %1, %2;" : "=l"(d) : "l"(a), "l"(b)); return d;
}
__device__ __forceinline__ float fast_exp(float x) {
    float y = fmaxf(x * 1.4426950408889634f, -126.0f);
    float n = rintf(y);
    float r = y - n;
    float q = 1.5403530394e-4f;
    q = fmaf(q, r, 1.3333558146e-3f);
    q = fmaf(q, r, 9.6181291076e-3f);
    q = fmaf(q, r, 5.5504108664e-2f);
    q = fmaf(q, r, 2.4022650696e-1f);
    q = fmaf(q, r, 6.9314718056e-1f);
    q = fmaf(q, r, 1.0f);
    return q * __int_as_float(((int)n + 127) << 23);
}

// ---------------- mma.sync helpers (portable PTX, no 'a' features) --------
__device__ __forceinline__ void ldm_x4(unsigned* r, unsigned saddr) {
    asm volatile("ldmatrix.sync.aligned.m8n8.x4.shared.b16 {%0,%1,%2,%3}, [%4];"
                 : "=r"(r[0]), "=r"(r[1]), "=r"(r[2]), "=r"(r[3]) : "r"(saddr));
}
__device__ __forceinline__ void mma_bf16(float* d, const unsigned* a, const unsigned* b) {
    asm volatile(
        "mma.sync.aligned.m16n8k16.row.col.f32.bf16.bf16.f32 "
        "{%0,%1,%2,%3}, {%4,%5,%6,%7}, {%8,%9}, {%0,%1,%2,%3};"
        : "+f"(d[0]), "+f"(d[1]), "+f"(d[2]), "+f"(d[3])
        : "r"(a[0]), "r"(a[1]), "r"(a[2]), "r"(a[3]), "r"(b[0]), "r"(b[1]));
}

// ---------------------------------------------------------------------------
// fp32 -> (hi, lo) bf16 split, vectorized.
// ---------------------------------------------------------------------------
__global__ void cvt_kernel(const float* __restrict__ x,
                           __nv_bfloat16* __restrict__ hi,
                           __nv_bfloat16* __restrict__ lo, int n4)
{
    int i = blockIdx.x * blockDim.x + threadIdx.x;
    if (i >= n4) return;
    float4 v = ((const float4*)x)[i];
    __nv_bfloat16 h0 = __float2bfloat16(v.x);
    __nv_bfloat16 h1 = __float2bfloat16(v.y);
    __nv_bfloat16 h2 = __float2bfloat16(v.z);
    __nv_bfloat16 h3 = __float2bfloat16(v.w);
    __nv_bfloat16 l0 = __float2bfloat16(v.x - __bfloat162float(h0));
    __nv_bfloat16 l1 = __float2bfloat16(v.y - __bfloat162float(h1));
    __nv_bfloat16 l2 = __float2bfloat16(v.z - __bfloat162float(h2));
    __nv_bfloat16 l3 = __float2bfloat16(v.w - __bfloat162float(h3));
    ((__nv_bfloat162*)hi)[2 * i]     = __halves2bfloat162(h0, h1);
    ((__nv_bfloat162*)hi)[2 * i + 1] = __halves2bfloat162(h2, h3);
    ((__nv_bfloat162*)lo)[2 * i]     = __halves2bfloat162(l0, l1);
    ((__nv_bfloat162*)lo)[2 * i + 1] = __halves2bfloat162(l2, l3);
}

// ---------------------------------------------------------------------------
// HMMA GEMM: C[M,512] = A[M,512] @ W[512,512]^T + bias, bf16-split 3 terms.
// Grid (4, M/128); CTA tile 128x128, BK=64; 8 warps (2x4), warp tile 64x32.
// A[M,K] and W[N,K] are both k-contiguous -> ldmatrix NON-trans gives the
// exact A- and B-fragment layouts for mma.m16n8k16.row.col.
// smem row stride 72 bf16 (144B): ldmatrix conflict-free (4r mod 32).
// ---------------------------------------------------------------------------
#define GP 72      // smem row pitch in bf16
#define GSMEM (4 * 128 * GP * 2)

__global__ __launch_bounds__(256) void hmma_gemm(
    const __nv_bfloat16* __restrict__ Ahi, const __nv_bfloat16* __restrict__ Alo,
    const __nv_bfloat16* __restrict__ Whi, const __nv_bfloat16* __restrict__ Wlo,
    const float* __restrict__ bias, float* __restrict__ C)
{
    extern __shared__ __nv_bfloat16 sb16[];
    __nv_bfloat16* sAhi = sb16;
    __nv_bfloat16* sAlo = sAhi + 128 * GP;
    __nv_bfloat16* sWhi = sAlo + 128 * GP;
    __nv_bfloat16* sWlo = sWhi + 128 * GP;

    const int tid  = threadIdx.x;
    const int w    = tid >> 5, lane = tid & 31;
    const int wm   = w >> 2, wn = w & 3;
    const int m0   = blockIdx.y * 128;
    const int n0   = blockIdx.x * 128;

    const unsigned uAhi = (unsigned)__cvta_generic_to_shared(sAhi);
    const unsigned uAlo = (unsigned)__cvta_generic_to_shared(sAlo);
    const unsigned uWhi = (unsigned)__cvta_generic_to_shared(sWhi);
    const unsigned uWlo = (unsigned)__cvta_generic_to_shared(sWlo);

    // ldmatrix per-lane addressing (matrix idx lm = lane>>3)
    const int aRow = wm * 64 + ((lane >> 3) & 1) * 8 + (lane & 7);  // + mi*16
    const int aK   = (lane >> 4) * 8;                               // + ks*16
    const int bRow = wn * 32 + (lane >> 4) * 8 + (lane & 7);        // + pr*16
    const int bK   = ((lane >> 3) & 1) * 8;                         // + ks*16

    float acc[4][4][4];
    #pragma unroll
    for (int i = 0; i < 4; i++)
        #pragma unroll
        for (int j = 0; j < 4; j++)
            #pragma unroll
            for (int r = 0; r < 4; r++) acc[i][j][r] = 0.0f;

    for (int c = 0; c < 8; c++) {
        const int k0 = c * 64;
        #pragma unroll
        for (int it = 0; it < 4; it++) {
            int idx = tid + it * 256;            // 0..1023
            int row = idx >> 3;                  // 0..127
            int sg  = (idx & 7) * 8;             // bf16 offset (16B segs)
            size_t ga = (size_t)(m0 + row) * 512 + k0 + sg;
            size_t gw = (size_t)(n0 + row) * 512 + k0 + sg;
            *(uint4*)&sAhi[row * GP + sg] = *(const uint4*)&Ahi[ga];
            *(uint4*)&sAlo[row * GP + sg] = *(const uint4*)&Alo[ga];
            *(uint4*)&sWhi[row * GP + sg] = *(const uint4*)&Whi[gw];
            *(uint4*)&sWlo[row * GP + sg] = *(const uint4*)&Wlo[gw];
        }
        __syncthreads();

        #pragma unroll
        for (int ks = 0; ks < 4; ks++) {
            unsigned ah[4][4], bh[4][2], bl[4][2];
            #pragma unroll
            for (int mi = 0; mi < 4; mi++)
                ldm_x4(ah[mi], uAhi + (unsigned)(((aRow + mi * 16) * GP + ks * 16 + aK) * 2));
            #pragma unroll
            for (int pr = 0; pr < 2; pr++) {
                unsigned t[4];
                ldm_x4(t, uWhi + (unsigned)(((bRow + pr * 16) * GP + ks * 16 + bK) * 2));
                bh[2 * pr][0] = t[0]; bh[2 * pr][1] = t[1];
                bh[2 * pr + 1][0] = t[2]; bh[2 * pr + 1][1] = t[3];
                ldm_x4(t, uWlo + (unsigned)(((bRow + pr * 16) * GP + ks * 16 + bK) * 2));
                bl[2 * pr][0] = t[0]; bl[2 * pr][1] = t[1];
                bl[2 * pr + 1][0] = t[2]; bl[2 * pr + 1][1] = t[3];
            }
            #pragma unroll
            for (int mi = 0; mi < 4; mi++)
                #pragma unroll
                for (int ns = 0; ns < 4; ns++) {
                    mma_bf16(acc[mi][ns], ah[mi], bh[ns]);   // hi*hi
                    mma_bf16(acc[mi][ns], ah[mi], bl[ns]);   // hi*lo
                }
            unsigned al[4][4];
            #pragma unroll
            for (int mi = 0; mi < 4; mi++)
                ldm_x4(al[mi], uAlo + (unsigned)(((aRow + mi * 16) * GP + ks * 16 + aK) * 2));
            #pragma unroll
            for (int mi = 0; mi < 4; mi++)
                #pragma unroll
                for (int ns = 0; ns < 4; ns++)
                    mma_bf16(acc[mi][ns], al[mi], bh[ns]);   // lo*hi
        }
        __syncthreads();
    }

    // epilogue
    const int g  = lane >> 2, tg = lane & 3;
    #pragma unroll
    for (int mi = 0; mi < 4; mi++) {
        #pragma unroll
        for (int ns = 0; ns < 4; ns++) {
            int row = m0 + wm * 64 + mi * 16 + g;
            int col = n0 + wn * 32 + ns * 8 + tg * 2;
            float2 bb = *(const float2*)&bias[col];
            float2 v0 = {acc[mi][ns][0] + bb.x, acc[mi][ns][1] + bb.y};
            float2 v1 = {acc[mi][ns][2] + bb.x, acc[mi][ns][3] + bb.y};
            *(float2*)&C[(size_t)row * 512 + col]       = v0;
            *(float2*)&C[(size_t)(row + 8) * 512 + col] = v1;
        }
    }
}

// ---------------------------------------------------------------------------
// Flash attention: 128-query tiles, 2 CTAs/SM (smem ~100KB, regs capped 128).
// tx: 8 keys/d each; ty: 4 queries each. FFMA2 + FMA-pipe exp.
// ---------------------------------------------------------------------------
__global__ __launch_bounds__(256, 2) void attn_kernel(const int* __restrict__ mask)
{
    extern __shared__ float sm[];
    float* Qs   = sm;                    // [64][132]  Q k-major
    float* Ks   = Qs + 64 * 132;         // [64][68]   K k-major
    float* Vs   = Ks + 64 * 68;          // [64][68]   V s-major
    float* Ps   = Vs + 64 * 68;          // [64][132]  P s-major (swizzled cols)
    float* mneg = Ps + 64 * 132;         // [64]

    const int tid = threadIdx.x;
    const int tx = tid & 7;
    const int ty = tid >> 3;             // 0..31, 4 queries each
    const int t0 = blockIdx.x * 128;
    const int h  = blockIdx.y;
    const int b  = blockIdx.z;

    // Load Q tile 128x64, transposed to k-major.
    #pragma unroll
    for (int r = 0; r < 8; r++) {
        int idx = tid + r * 256;
        int row = idx >> 4;              // 0..127
        int c4  = (idx & 15) * 4;
        float4 q = *(const float4*)&g_Q[((size_t)(b * Tv + t0 + row)) * HIDv + h * DKv + c4];
        Qs[(c4 + 0) * 132 + row] = q.x;
        Qs[(c4 + 1) * 132 + row] = q.y;
        Qs[(c4 + 2) * 132 + row] = q.z;
        Qs[(c4 + 3) * 132 + row] = q.w;
    }

    float rowM[4], rowL[4];
    #pragma unroll
    for (int i = 0; i < 4; i++) { rowM[i] = -1e30f; rowL[i] = 0.0f; }

    u64 acc2[4][4];
    #pragma unroll
    for (int i = 0; i < 4; i++)
        #pragma unroll
        for (int j = 0; j < 4; j++) acc2[i][j] = 0ull;

    const int Xst = (tx & 3) << 2;
    __syncthreads();

    for (int s0 = 0; s0 < Sv; s0 += 64) {
        #pragma unroll
        for (int r = 0; r < 4; r++) {
            int idx = tid + r * 256;
            int row = idx >> 4;
            int c4  = (idx & 15) * 4;
            size_t g = ((size_t)(b * Sv + s0 + row)) * HIDv + h * DKv + c4;
            float4 k = *(const float4*)&g_K[g];
            Ks[(c4 + 0) * 68 + row] = k.x;
            Ks[(c4 + 1) * 68 + row] = k.y;
            Ks[(c4 + 2) * 68 + row] = k.z;
            Ks[(c4 + 3) * 68 + row] = k.w;
            float4 v = *(const float4*)&g_V[g];
            *(float4*)&Vs[row * 68 + c4] = v;
        }
        if (tid < 64) mneg[tid] = (mask[b * Sv + s0 + tid] != 0) ? 0.0f : -1e20f;
        __syncthreads();

        // QK^T: sc2[query][keypair]
        u64 sc2[4][4];
        #pragma unroll
        for (int i = 0; i < 4; i++)
            #pragma unroll
            for (int j = 0; j < 4; j++) sc2[i][j] = 0ull;

        #pragma unroll 8
        for (int kk = 0; kk < 64; kk++) {
            float4 a0 = *(const float4*)&Qs[kk * 132 + ty * 4];
            ulonglong2 b0 = *(const ulonglong2*)&Ks[kk * 68 + tx * 8];
            ulonglong2 b1 = *(const ulonglong2*)&Ks[kk * 68 + tx * 8 + 4];
            u64 bb2[4] = {b0.x, b0.y, b1.x, b1.y};
            u64 a2[4];
            a2[0] = pdup(a0.x); a2[1] = pdup(a0.y);
            a2[2] = pdup(a0.z); a2[3] = pdup(a0.w);
            #pragma unroll
            for (int i = 0; i < 4; i++)
                #pragma unroll
                for (int j = 0; j < 4; j++)
                    sc2[i][j] = fma2(a2[i], bb2[j], sc2[i][j]);
        }

        // scale + mask
        {
            ulonglong2 m0 = *(const ulonglong2*)&mneg[tx * 8];
            ulonglong2 m1 = *(const ulonglong2*)&mneg[tx * 8 + 4];
            u64 mm[4] = {m0.x, m0.y, m1.x, m1.y};
            u64 c18 = pdup(0.125f);
            #pragma unroll
            for (int i = 0; i < 4; i++)
                #pragma unroll
                for (int j = 0; j < 4; j++)
                    sc2[i][j] = fma2(sc2[i][j], c18, mm[j]);
        }

        // Online softmax per query row (8 lanes/row, shfl width 8).
        #pragma unroll
        for (int i = 0; i < 4; i++) {
            float s8[8];
            unpack2(sc2[i][0], s8[0], s8[1]);
            unpack2(sc2[i][1], s8[2], s8[3]);
            unpack2(sc2[i][2], s8[4], s8[5]);
            unpack2(sc2[i][3], s8[6], s8[7]);
            float mx = fmaxf(fmaxf(fmaxf(s8[0], s8[1]), fmaxf(s8[2], s8[3])),
                             fmaxf(fmaxf(s8[4], s8[5]), fmaxf(s8[6], s8[7])));
            #pragma unroll
            for (int o = 4; o >= 1; o >>= 1)
                mx = fmaxf(mx, __shfl_xor_sync(0xffffffffu, mx, o, 8));

            float mnw = fmaxf(rowM[i], mx);
            float f   = fast_exp(rowM[i] - mnw);
            rowM[i] = mnw;

            float p[8], se = 0.0f;
            #pragma unroll
            for (int k = 0; k < 8; k++) { p[k] = fast_exp(s8[k] - mnw); se += p[k]; }
            #pragma unroll
            for (int o = 4; o >= 1; o >>= 1)
                se += __shfl_xor_sync(0xffffffffu, se, o, 8);
            rowL[i] = rowL[i] * f + se;

            u64 f2 = pdup(f);
            #pragma unroll
            for (int j = 0; j < 4; j++) acc2[i][j] = mul2(acc2[i][j], f2);

            int colp = (ty * 4 + i) ^ Xst;
            #pragma unroll
            for (int j = 0; j < 8; j++)
                Ps[(tx * 8 + j) * 132 + colp] = p[j];
        }
        __syncthreads();

        // acc += P @ V  (single float4 de-swizzled P load per s)
        #pragma unroll 4
        for (int s = 0; s < 64; s++) {
            int X = ((s >> 3) & 3) << 2;
            float4 pq = *(const float4*)&Ps[s * 132 + ((ty * 4) ^ X)];
            u64 pp[4] = {pdup(pq.x), pdup(pq.y), pdup(pq.z), pdup(pq.w)};
            ulonglong2 v0 = *(const ulonglong2*)&Vs[s * 68 + tx * 8];
            ulonglong2 v1 = *(const ulonglong2*)&Vs[s * 68 + tx * 8 + 4];
            u64 vv[4] = {v0.x, v0.y, v1.x, v1.y};
            #pragma unroll
            for (int i = 0; i < 4; i++)
                #pragma unroll
                for (int j = 0; j < 4; j++)
                    acc2[i][j] = fma2(pp[i], vv[j], acc2[i][j]);
        }
        __syncthreads();
    }

    // normalize + write ctx
    #pragma unroll
    for (int i = 0; i < 4; i++) {
        float inv = 1.0f / rowL[i];
        float o[8];
        unpack2(acc2[i][0], o[0], o[1]);
        unpack2(acc2[i][1], o[2], o[3]);
        unpack2(acc2[i][2], o[4], o[5]);
        unpack2(acc2[i][3], o[6], o[7]);
        float4 s0, s1;
        s0.x = o[0] * inv; s0.y = o[1] * inv; s0.z = o[2] * inv; s0.w = o[3] * inv;
        s1.x = o[4] * inv; s1.y = o[5] * inv; s1.z = o[6] * inv; s1.w = o[7] * inv;
        size_t base = ((size_t)(b * Tv + t0 + ty * 4 + i)) * HIDv + h * DKv + tx * 8;
        *(float4*)&g_ctx[base]     = s0;
        *(float4*)&g_ctx[base + 4] = s1;
    }
}

// ---------------------------------------------------------------------------

extern "C" void kernel_launch(void* const* d_in, const int* in_sizes, int n_in,
                              void* d_out, int out_size)
{
    const float* inputs  = (const float*)d_in[0];
    const float* targets = (const float*)d_in[1];
    const int*   mask    = (const int*)d_in[2];     // bool widened to int32
    const float* Wq = (const float*)d_in[3];
    const float* bq = (const float*)d_in[4];
    const float* Wk = (const float*)d_in[5];
    const float* bk = (const float*)d_in[6];
    const float* Wv = (const float*)d_in[7];
    const float* bv = (const float*)d_in[8];
    const float* Wo = (const float*)d_in[9];
    const float* bo = (const float*)d_in[10];
    float* out = (float*)d_out;

    float *pQ, *pK, *pV, *pC;
    cudaGetSymbolAddress((void**)&pQ, g_Q);
    cudaGetSymbolAddress((void**)&pK, g_K);
    cudaGetSymbolAddress((void**)&pV, g_V);
    cudaGetSymbolAddress((void**)&pC, g_ctx);
    __nv_bfloat16 *inH, *inL, *tgH, *tgL, *cxH, *cxL, *wH, *wL;
    cudaGetSymbolAddress((void**)&inH, g_in_hi);
    cudaGetSymbolAddress((void**)&inL, g_in_lo);
    cudaGetSymbolAddress((void**)&tgH, g_tg_hi);
    cudaGetSymbolAddress((void**)&tgL, g_tg_lo);
    cudaGetSymbolAddress((void**)&cxH, g_cx_hi);
    cudaGetSymbolAddress((void**)&cxL, g_cx_lo);
    cudaGetSymbolAddress((void**)&wH, g_w_hi);
    cudaGetSymbolAddress((void**)&wL, g_w_lo);

    const int ATTN_SMEM = (64 * 132 + 64 * 68 + 64 * 68 + 64 * 132 + 64) * (int)sizeof(float);
    cudaFuncSetAttribute(attn_kernel, cudaFuncAttributeMaxDynamicSharedMemorySize, ATTN_SMEM);
    cudaFuncSetAttribute(hmma_gemm, cudaFuncAttributeMaxDynamicSharedMemorySize, GSMEM);

    const int W_ELEMS = HIDv * HIDv;
    cvt_kernel<<<(Bv * Tv * HIDv / 4 + 255) / 256, 256>>>(targets, tgH, tgL, Bv * Tv * HIDv / 4);
    cvt_kernel<<<(Bv * Sv * HIDv / 4 + 255) / 256, 256>>>(inputs, inH, inL, Bv * Sv * HIDv / 4);
    cvt_kernel<<<(W_ELEMS / 4 + 255) / 256, 256>>>(Wq, wH + 0 * W_ELEMS, wL + 0 * W_ELEMS, W_ELEMS / 4);
    cvt_kernel<<<(W_ELEMS / 4 + 255) / 256, 256>>>(Wk, wH + 1 * W_ELEMS, wL + 1 * W_ELEMS, W_ELEMS / 4);
    cvt_kernel<<<(W_ELEMS / 4 + 255) / 256, 256>>>(Wv, wH + 2 * W_ELEMS, wL + 2 * W_ELEMS, W_ELEMS / 4);
    cvt_kernel<<<(W_ELEMS / 4 + 255) / 256, 256>>>(Wo, wH + 3 * W_ELEMS, wL + 3 * W_ELEMS, W_ELEMS / 4);

    hmma_gemm<<<dim3(4, Bv * Tv / 128), 256, GSMEM>>>(tgH, tgL, wH + 0 * W_ELEMS, wL + 0 * W_ELEMS, bq, pQ);
    hmma_gemm<<<dim3(4, Bv * Sv / 128), 256, GSMEM>>>(inH, inL, wH + 1 * W_ELEMS, wL + 1 * W_ELEMS, bk, pK);
    hmma_gemm<<<dim3(4, Bv * Sv / 128), 256, GSMEM>>>(inH, inL, wH + 2 * W_ELEMS, wL + 2 * W_ELEMS, bv, pV);

    attn_kernel<<<dim3(Tv / 128, HEADSv, Bv), 256, ATTN_SMEM>>>(mask);

    cvt_kernel<<<(Bv * Tv * HIDv / 4 + 255) / 256, 256>>>(pC, cxH, cxL, Bv * Tv * HIDv / 4);
    hmma_gemm<<<dim3(4, Bv * Tv / 128), 256, GSMEM>>>(cxH, cxL, wH + 3 * W_ELEMS, wL + 3 * W_ELEMS, bo, out);
}

// round 12
// speedup vs baseline: 2.8248x; 1.0082x over previous
#include <cuda_runtime.h>
#include <cuda_bf16.h>
#include <math.h>

#define Bv    8
#define Sv    4096
#define Tv    512
#define HIDv  512
#define HEADSv 8
#define DKv   64

typedef unsigned long long u64;

// ------------------------- scratch (__device__ globals) --------------------
__device__ float g_Q[Bv * Tv * HIDv];
__device__ float g_K[Bv * Sv * HIDv];
__device__ float g_V[Bv * Sv * HIDv];
__device__ float g_ctx[Bv * Tv * HIDv];
__device__ __nv_bfloat16 g_in_hi[Bv * Sv * HIDv];
__device__ __nv_bfloat16 g_in_lo[Bv * Sv * HIDv];
__device__ __nv_bfloat16 g_tg_hi[Bv * Tv * HIDv];
__device__ __nv_bfloat16 g_tg_lo[Bv * Tv * HIDv];
__device__ __nv_bfloat16 g_cx_hi[Bv * Tv * HIDv];
__device__ __nv_bfloat16 g_cx_lo[Bv * Tv * HIDv];
__device__ __nv_bfloat16 g_w_hi[4 * HIDv * HIDv];
__device__ __nv_bfloat16 g_w_lo[4 * HIDv * HIDv];

// ---------------- packed f32x2 helpers (FFMA2, attention) ------------------
__device__ __forceinline__ u64 pack2(float x, float y) {
    u64 d; asm("mov.b64 %0, {%1, %2};" : "=l"(d) : "f"(x), "f"(y)); return d;
}
__device__ __forceinline__ u64 pdup(float x) { return pack2(x, x); }
__device__ __forceinline__ void unpack2(u64 v, float& x, float& y) {
    asm("mov.b64 {%0, %1}, %2;" : "=f"(x), "=f"(y) : "l"(v));
}
__device__ __forceinline__ u64 fma2(u64 a, u64 b, u64 c) {
    u64 d; asm("fma.rn.f32x2 %0, %1, %2, %3;" : "=l"(d) : "l"(a), "l"(b), "l"(c)); return d;
}
__device__ __forceinline__ u64 mul2(u64 a, u64 b) {
    u64 d; asm("mul.rn.f32x2 %0, %1, %2;" : "=l"(d) : "l"(a), "l"(b)); return d;
}
__device__ __forceinline__ float fast_exp(float x) {
    float y = fmaxf(x * 1.4426950408889634f, -126.0f);
    float n = rintf(y);
    float r = y - n;
    float q = 1.5403530394e-4f;
    q = fmaf(q, r, 1.3333558146e-3f);
    q = fmaf(q, r, 9.6181291076e-3f);
    q = fmaf(q, r, 5.5504108664e-2f);
    q = fmaf(q, r, 2.4022650696e-1f);
    q = fmaf(q, r, 6.9314718056e-1f);
    q = fmaf(q, r, 1.0f);
    return q * __int_as_float(((int)n + 127) << 23);
}

// ---------------- mma.sync helpers (portable PTX, no 'a' features) --------
__device__ __forceinline__ void ldm_x4(unsigned* r, unsigned saddr) {
    asm volatile("ldmatrix.sync.aligned.m8n8.x4.shared.b16 {%0,%1,%2,%3}, [%4];"
                 : "=r"(r[0]), "=r"(r[1]), "=r"(r[2]), "=r"(r[3]) : "r"(saddr));
}
__device__ __forceinline__ void mma_bf16(float* d, const unsigned* a, const unsigned* b) {
    asm volatile(
        "mma.sync.aligned.m16n8k16.row.col.f32.bf16.bf16.f32 "
        "{%0,%1,%2,%3}, {%4,%5,%6,%7}, {%8,%9}, {%0,%1,%2,%3};"
        : "+f"(d[0]), "+f"(d[1]), "+f"(d[2]), "+f"(d[3])
        : "r"(a[0]), "r"(a[1]), "r"(a[2]), "r"(a[3]), "r"(b[0]), "r"(b[1]));
}

// ---------------------------------------------------------------------------
// fp32 -> (hi, lo) bf16 split, vectorized.
// ---------------------------------------------------------------------------
__global__ void cvt_kernel(const float* __restrict__ x,
                           __nv_bfloat16* __restrict__ hi,
                           __nv_bfloat16* __restrict__ lo, int n4)
{
    int i = blockIdx.x * blockDim.x + threadIdx.x;
    if (i >= n4) return;
    float4 v = ((const float4*)x)[i];
    __nv_bfloat16 h0 = __float2bfloat16(v.x);
    __nv_bfloat16 h1 = __float2bfloat16(v.y);
    __nv_bfloat16 h2 = __float2bfloat16(v.z);
    __nv_bfloat16 h3 = __float2bfloat16(v.w);
    __nv_bfloat16 l0 = __float2bfloat16(v.x - __bfloat162float(h0));
    __nv_bfloat16 l1 = __float2bfloat16(v.y - __bfloat162float(h1));
    __nv_bfloat16 l2 = __float2bfloat16(v.z - __bfloat162float(h2));
    __nv_bfloat16 l3 = __float2bfloat16(v.w - __bfloat162float(h3));
    ((__nv_bfloat162*)hi)[2 * i]     = __halves2bfloat162(h0, h1);
    ((__nv_bfloat162*)hi)[2 * i + 1] = __halves2bfloat162(h2, h3);
    ((__nv_bfloat162*)lo)[2 * i]     = __halves2bfloat162(l0, l1);
    ((__nv_bfloat162*)lo)[2 * i + 1] = __halves2bfloat162(l2, l3);
}

// ---------------------------------------------------------------------------
// HMMA GEMM: C[M,512] = A[M,512] @ W[512,512]^T + bias, bf16-split 3 terms.
// Grid (4, M/128); CTA tile 128x128, BK=64; 8 warps (2x4), warp tile 64x32.
// __launch_bounds__(256,2): 2 CTAs/SM so one CTA's MMA phase overlaps the
// other's global->smem fill (cheap double buffering).
// ---------------------------------------------------------------------------
#define GP 72      // smem row pitch in bf16
#define GSMEM (4 * 128 * GP * 2)

__global__ __launch_bounds__(256, 2) void hmma_gemm(
    const __nv_bfloat16* __restrict__ Ahi, const __nv_bfloat16* __restrict__ Alo,
    const __nv_bfloat16* __restrict__ Whi, const __nv_bfloat16* __restrict__ Wlo,
    const float* __restrict__ bias, float* __restrict__ C)
{
    extern __shared__ __nv_bfloat16 sb16[];
    __nv_bfloat16* sAhi = sb16;
    __nv_bfloat16* sAlo = sAhi + 128 * GP;
    __nv_bfloat16* sWhi = sAlo + 128 * GP;
    __nv_bfloat16* sWlo = sWhi + 128 * GP;

    const int tid  = threadIdx.x;
    const int w    = tid >> 5, lane = tid & 31;
    const int wm   = w >> 2, wn = w & 3;
    const int m0   = blockIdx.y * 128;
    const int n0   = blockIdx.x * 128;

    const unsigned uAhi = (unsigned)__cvta_generic_to_shared(sAhi);
    const unsigned uAlo = (unsigned)__cvta_generic_to_shared(sAlo);
    const unsigned uWhi = (unsigned)__cvta_generic_to_shared(sWhi);
    const unsigned uWlo = (unsigned)__cvta_generic_to_shared(sWlo);

    const int aRow = wm * 64 + ((lane >> 3) & 1) * 8 + (lane & 7);  // + mi*16
    const int aK   = (lane >> 4) * 8;                               // + ks*16
    const int bRow = wn * 32 + (lane >> 4) * 8 + (lane & 7);        // + pr*16
    const int bK   = ((lane >> 3) & 1) * 8;                         // + ks*16

    float acc[4][4][4];
    #pragma unroll
    for (int i = 0; i < 4; i++)
        #pragma unroll
        for (int j = 0; j < 4; j++)
            #pragma unroll
            for (int r = 0; r < 4; r++) acc[i][j][r] = 0.0f;

    for (int c = 0; c < 8; c++) {
        const int k0 = c * 64;
        #pragma unroll
        for (int it = 0; it < 4; it++) {
            int idx = tid + it * 256;            // 0..1023
            int row = idx >> 3;                  // 0..127
            int sg  = (idx & 7) * 8;             // bf16 offset (16B segs)
            size_t ga = (size_t)(m0 + row) * 512 + k0 + sg;
            size_t gw = (size_t)(n0 + row) * 512 + k0 + sg;
            *(uint4*)&sAhi[row * GP + sg] = *(const uint4*)&Ahi[ga];
            *(uint4*)&sAlo[row * GP + sg] = *(const uint4*)&Alo[ga];
            *(uint4*)&sWhi[row * GP + sg] = *(const uint4*)&Whi[gw];
            *(uint4*)&sWlo[row * GP + sg] = *(const uint4*)&Wlo[gw];
        }
        __syncthreads();

        #pragma unroll
        for (int ks = 0; ks < 4; ks++) {
            unsigned ah[4][4], bh[4][2], bl[4][2];
            #pragma unroll
            for (int mi = 0; mi < 4; mi++)
                ldm_x4(ah[mi], uAhi + (unsigned)(((aRow + mi * 16) * GP + ks * 16 + aK) * 2));
            #pragma unroll
            for (int pr = 0; pr < 2; pr++) {
                unsigned t[4];
                ldm_x4(t, uWhi + (unsigned)(((bRow + pr * 16) * GP + ks * 16 + bK) * 2));
                bh[2 * pr][0] = t[0]; bh[2 * pr][1] = t[1];
                bh[2 * pr + 1][0] = t[2]; bh[2 * pr + 1][1] = t[3];
                ldm_x4(t, uWlo + (unsigned)(((bRow + pr * 16) * GP + ks * 16 + bK) * 2));
                bl[2 * pr][0] = t[0]; bl[2 * pr][1] = t[1];
                bl[2 * pr + 1][0] = t[2]; bl[2 * pr + 1][1] = t[3];
            }
            #pragma unroll
            for (int mi = 0; mi < 4; mi++)
                #pragma unroll
                for (int ns = 0; ns < 4; ns++) {
                    mma_bf16(acc[mi][ns], ah[mi], bh[ns]);   // hi*hi
                    mma_bf16(acc[mi][ns], ah[mi], bl[ns]);   // hi*lo
                }
            unsigned al[4][4];
            #pragma unroll
            for (int mi = 0; mi < 4; mi++)
                ldm_x4(al[mi], uAlo + (unsigned)(((aRow + mi * 16) * GP + ks * 16 + aK) * 2));
            #pragma unroll
            for (int mi = 0; mi < 4; mi++)
                #pragma unroll
                for (int ns = 0; ns < 4; ns++)
                    mma_bf16(acc[mi][ns], al[mi], bh[ns]);   // lo*hi
        }
        __syncthreads();
    }

    // epilogue
    const int g  = lane >> 2, tg = lane & 3;
    #pragma unroll
    for (int mi = 0; mi < 4; mi++) {
        #pragma unroll
        for (int ns = 0; ns < 4; ns++) {
            int row = m0 + wm * 64 + mi * 16 + g;
            int col = n0 + wn * 32 + ns * 8 + tg * 2;
            float2 bb = *(const float2*)&bias[col];
            float2 v0 = {acc[mi][ns][0] + bb.x, acc[mi][ns][1] + bb.y};
            float2 v1 = {acc[mi][ns][2] + bb.x, acc[mi][ns][3] + bb.y};
            *(float2*)&C[(size_t)row * 512 + col]       = v0;
            *(float2*)&C[(size_t)(row + 8) * 512 + col] = v1;
        }
    }
}

// ---------------------------------------------------------------------------
// Flash attention: 128-query tiles, 2 CTAs/SM (UNCHANGED from round 11).
// ---------------------------------------------------------------------------
__global__ __launch_bounds__(256, 2) void attn_kernel(const int* __restrict__ mask)
{
    extern __shared__ float sm[];
    float* Qs   = sm;                    // [64][132]  Q k-major
    float* Ks   = Qs + 64 * 132;         // [64][68]   K k-major
    float* Vs   = Ks + 64 * 68;          // [64][68]   V s-major
    float* Ps   = Vs + 64 * 68;          // [64][132]  P s-major (swizzled cols)
    float* mneg = Ps + 64 * 132;         // [64]

    const int tid = threadIdx.x;
    const int tx = tid & 7;
    const int ty = tid >> 3;             // 0..31, 4 queries each
    const int t0 = blockIdx.x * 128;
    const int h  = blockIdx.y;
    const int b  = blockIdx.z;

    #pragma unroll
    for (int r = 0; r < 8; r++) {
        int idx = tid + r * 256;
        int row = idx >> 4;              // 0..127
        int c4  = (idx & 15) * 4;
        float4 q = *(const float4*)&g_Q[((size_t)(b * Tv + t0 + row)) * HIDv + h * DKv + c4];
        Qs[(c4 + 0) * 132 + row] = q.x;
        Qs[(c4 + 1) * 132 + row] = q.y;
        Qs[(c4 + 2) * 132 + row] = q.z;
        Qs[(c4 + 3) * 132 + row] = q.w;
    }

    float rowM[4], rowL[4];
    #pragma unroll
    for (int i = 0; i < 4; i++) { rowM[i] = -1e30f; rowL[i] = 0.0f; }

    u64 acc2[4][4];
    #pragma unroll
    for (int i = 0; i < 4; i++)
        #pragma unroll
        for (int j = 0; j < 4; j++) acc2[i][j] = 0ull;

    const int Xst = (tx & 3) << 2;
    __syncthreads();

    for (int s0 = 0; s0 < Sv; s0 += 64) {
        #pragma unroll
        for (int r = 0; r < 4; r++) {
            int idx = tid + r * 256;
            int row = idx >> 4;
            int c4  = (idx & 15) * 4;
            size_t g = ((size_t)(b * Sv + s0 + row)) * HIDv + h * DKv + c4;
            float4 k = *(const float4*)&g_K[g];
            Ks[(c4 + 0) * 68 + row] = k.x;
            Ks[(c4 + 1) * 68 + row] = k.y;
            Ks[(c4 + 2) * 68 + row] = k.z;
            Ks[(c4 + 3) * 68 + row] = k.w;
            float4 v = *(const float4*)&g_V[g];
            *(float4*)&Vs[row * 68 + c4] = v;
        }
        if (tid < 64) mneg[tid] = (mask[b * Sv + s0 + tid] != 0) ? 0.0f : -1e20f;
        __syncthreads();

        u64 sc2[4][4];
        #pragma unroll
        for (int i = 0; i < 4; i++)
            #pragma unroll
            for (int j = 0; j < 4; j++) sc2[i][j] = 0ull;

        #pragma unroll 8
        for (int kk = 0; kk < 64; kk++) {
            float4 a0 = *(const float4*)&Qs[kk * 132 + ty * 4];
            ulonglong2 b0 = *(const ulonglong2*)&Ks[kk * 68 + tx * 8];
            ulonglong2 b1 = *(const ulonglong2*)&Ks[kk * 68 + tx * 8 + 4];
            u64 bb2[4] = {b0.x, b0.y, b1.x, b1.y};
            u64 a2[4];
            a2[0] = pdup(a0.x); a2[1] = pdup(a0.y);
            a2[2] = pdup(a0.z); a2[3] = pdup(a0.w);
            #pragma unroll
            for (int i = 0; i < 4; i++)
                #pragma unroll
                for (int j = 0; j < 4; j++)
                    sc2[i][j] = fma2(a2[i], bb2[j], sc2[i][j]);
        }

        {
            ulonglong2 m0 = *(const ulonglong2*)&mneg[tx * 8];
            ulonglong2 m1 = *(const ulonglong2*)&mneg[tx * 8 + 4];
            u64 mm[4] = {m0.x, m0.y, m1.x, m1.y};
            u64 c18 = pdup(0.125f);
            #pragma unroll
            for (int i = 0; i < 4; i++)
                #pragma unroll
                for (int j = 0; j < 4; j++)
                    sc2[i][j] = fma2(sc2[i][j], c18, mm[j]);
        }

        #pragma unroll
        for (int i = 0; i < 4; i++) {
            float s8[8];
            unpack2(sc2[i][0], s8[0], s8[1]);
            unpack2(sc2[i][1], s8[2], s8[3]);
            unpack2(sc2[i][2], s8[4], s8[5]);
            unpack2(sc2[i][3], s8[6], s8[7]);
            float mx = fmaxf(fmaxf(fmaxf(s8[0], s8[1]), fmaxf(s8[2], s8[3])),
                             fmaxf(fmaxf(s8[4], s8[5]), fmaxf(s8[6], s8[7])));
            #pragma unroll
            for (int o = 4; o >= 1; o >>= 1)
                mx = fmaxf(mx, __shfl_xor_sync(0xffffffffu, mx, o, 8));

            float mnw = fmaxf(rowM[i], mx);
            float f   = fast_exp(rowM[i] - mnw);
            rowM[i] = mnw;

            float p[8], se = 0.0f;
            #pragma unroll
            for (int k = 0; k < 8; k++) { p[k] = fast_exp(s8[k] - mnw); se += p[k]; }
            #pragma unroll
            for (int o = 4; o >= 1; o >>= 1)
                se += __shfl_xor_sync(0xffffffffu, se, o, 8);
            rowL[i] = rowL[i] * f + se;

            u64 f2 = pdup(f);
            #pragma unroll
            for (int j = 0; j < 4; j++) acc2[i][j] = mul2(acc2[i][j], f2);

            int colp = (ty * 4 + i) ^ Xst;
            #pragma unroll
            for (int j = 0; j < 8; j++)
                Ps[(tx * 8 + j) * 132 + colp] = p[j];
        }
        __syncthreads();

        #pragma unroll 4
        for (int s = 0; s < 64; s++) {
            int X = ((s >> 3) & 3) << 2;
            float4 pq = *(const float4*)&Ps[s * 132 + ((ty * 4) ^ X)];
            u64 pp[4] = {pdup(pq.x), pdup(pq.y), pdup(pq.z), pdup(pq.w)};
            ulonglong2 v0 = *(const ulonglong2*)&Vs[s * 68 + tx * 8];
            ulonglong2 v1 = *(const ulonglong2*)&Vs[s * 68 + tx * 8 + 4];
            u64 vv[4] = {v0.x, v0.y, v1.x, v1.y};
            #pragma unroll
            for (int i = 0; i < 4; i++)
                #pragma unroll
                for (int j = 0; j < 4; j++)
                    acc2[i][j] = fma2(pp[i], vv[j], acc2[i][j]);
        }
        __syncthreads();
    }

    #pragma unroll
    for (int i = 0; i < 4; i++) {
        float inv = 1.0f / rowL[i];
        float o[8];
        unpack2(acc2[i][0], o[0], o[1]);
        unpack2(acc2[i][1], o[2], o[3]);
        unpack2(acc2[i][2], o[4], o[5]);
        unpack2(acc2[i][3], o[6], o[7]);
        float4 s0, s1;
        s0.x = o[0] * inv; s0.y = o[1] * inv; s0.z = o[2] * inv; s0.w = o[3] * inv;
        s1.x = o[4] * inv; s1.y = o[5] * inv; s1.z = o[6] * inv; s1.w = o[7] * inv;
        size_t base = ((size_t)(b * Tv + t0 + ty * 4 + i)) * HIDv + h * DKv + tx * 8;
        *(float4*)&g_ctx[base]     = s0;
        *(float4*)&g_ctx[base + 4] = s1;
    }
}

// ---------------------------------------------------------------------------

extern "C" void kernel_launch(void* const* d_in, const int* in_sizes, int n_in,
                              void* d_out, int out_size)
{
    const float* inputs  = (const float*)d_in[0];
    const float* targets = (const float*)d_in[1];
    const int*   mask    = (const int*)d_in[2];     // bool widened to int32
    const float* Wq = (const float*)d_in[3];
    const float* bq = (const float*)d_in[4];
    const float* Wk = (const float*)d_in[5];
    const float* bk = (const float*)d_in[6];
    const float* Wv = (const float*)d_in[7];
    const float* bv = (const float*)d_in[8];
    const float* Wo = (const float*)d_in[9];
    const float* bo = (const float*)d_in[10];
    float* out = (float*)d_out;

    float *pQ, *pK, *pV, *pC;
    cudaGetSymbolAddress((void**)&pQ, g_Q);
    cudaGetSymbolAddress((void**)&pK, g_K);
    cudaGetSymbolAddress((void**)&pV, g_V);
    cudaGetSymbolAddress((void**)&pC, g_ctx);
    __nv_bfloat16 *inH, *inL, *tgH, *tgL, *cxH, *cxL, *wH, *wL;
    cudaGetSymbolAddress((void**)&inH, g_in_hi);
    cudaGetSymbolAddress((void**)&inL, g_in_lo);
    cudaGetSymbolAddress((void**)&tgH, g_tg_hi);
    cudaGetSymbolAddress((void**)&tgL, g_tg_lo);
    cudaGetSymbolAddress((void**)&cxH, g_cx_hi);
    cudaGetSymbolAddress((void**)&cxL, g_cx_lo);
    cudaGetSymbolAddress((void**)&wH, g_w_hi);
    cudaGetSymbolAddress((void**)&wL, g_w_lo);

    const int ATTN_SMEM = (64 * 132 + 64 * 68 + 64 * 68 + 64 * 132 + 64) * (int)sizeof(float);
    cudaFuncSetAttribute(attn_kernel, cudaFuncAttributeMaxDynamicSharedMemorySize, ATTN_SMEM);
    cudaFuncSetAttribute(hmma_gemm, cudaFuncAttributeMaxDynamicSharedMemorySize, GSMEM);

    const int W_ELEMS = HIDv * HIDv;
    // Exactly 5 launches before the K-projection gemm, so the ncu capture
    // (6th kernel launch) lands on hmma_gemm for K.
    cvt_kernel<<<(Bv * Sv * HIDv / 4 + 255) / 256, 256>>>(inputs, inH, inL, Bv * Sv * HIDv / 4);
    cvt_kernel<<<(Bv * Tv * HIDv / 4 + 255) / 256, 256>>>(targets, tgH, tgL, Bv * Tv * HIDv / 4);
    cvt_kernel<<<(W_ELEMS / 4 + 255) / 256, 256>>>(Wk, wH + 1 * W_ELEMS, wL + 1 * W_ELEMS, W_ELEMS / 4);
    cvt_kernel<<<(W_ELEMS / 4 + 255) / 256, 256>>>(Wv, wH + 2 * W_ELEMS, wL + 2 * W_ELEMS, W_ELEMS / 4);
    cvt_kernel<<<(W_ELEMS / 4 + 255) / 256, 256>>>(Wq, wH + 0 * W_ELEMS, wL + 0 * W_ELEMS, W_ELEMS / 4);

    hmma_gemm<<<dim3(4, Bv * Sv / 128), 256, GSMEM>>>(inH, inL, wH + 1 * W_ELEMS, wL + 1 * W_ELEMS, bk, pK);
    hmma_gemm<<<dim3(4, Bv * Sv / 128), 256, GSMEM>>>(inH, inL, wH + 2 * W_ELEMS, wL + 2 * W_ELEMS, bv, pV);
    hmma_gemm<<<dim3(4, Bv * Tv / 128), 256, GSMEM>>>(tgH, tgL, wH + 0 * W_ELEMS, wL + 0 * W_ELEMS, bq, pQ);

    attn_kernel<<<dim3(Tv / 128, HEADSv, Bv), 256, ATTN_SMEM>>>(mask);

    cvt_kernel<<<(Bv * Tv * HIDv / 4 + 255) / 256, 256>>>(pC, cxH, cxL, Bv * Tv * HIDv / 4);
    cvt_kernel<<<(W_ELEMS / 4 + 255) / 256, 256>>>(Wo, wH + 3 * W_ELEMS, wL + 3 * W_ELEMS, W_ELEMS / 4);
    hmma_gemm<<<dim3(4, Bv * Tv / 128), 256, GSMEM>>>(cxH, cxL, wH + 3 * W_ELEMS, wL + 3 * W_ELEMS, bo, out);
}